// round 15
// baseline (speedup 1.0000x reference)
#include <cuda_runtime.h>
#include <cuda_bf16.h>
#include <cuda_fp16.h>
#include <math.h>
#include <stdint.h>

// Problem dims
#define BSZ 16
#define LEN 512
#define HIDD 768
#define NH 12
#define HD 64
#define R2V 16
#define GM (BSZ*LEN)          // 8192 rows
#define GN HIDD
#define GK HIDD
#define NW (768*768)

#define LOSCALE 1024.0f
#define INV_LOSCALE 0.0009765625f

// ---------------- scratch (device globals) ------------------------------------
__device__ __align__(16) __half g_V1h[(size_t)GM * GN];    // fp16 V1 (relu >= 0)
__device__ __align__(16) __half g_Ahi[(size_t)GM * GK];
__device__ __align__(16) __half g_Alo[(size_t)GM * GK];    // (a - hi) * 1024
__device__ __align__(16) __half g_Whi[2 * NW];
__device__ __align__(16) __half g_Wlo[2 * NW];             // (w - hi) * 1024
__device__ float g_scores[BSZ * NH * LEN];
__device__ int   g_idx[BSZ * NH * LEN * R2V];

// ---------------- PTX helpers (sm_80-baseline only) ----------------------------
__device__ __forceinline__ uint32_t smem_u32(const void* p) {
    uint32_t a;
    asm("{ .reg .u64 t; cvta.to.shared.u64 t, %1; cvt.u32.u64 %0, t; }" : "=r"(a) : "l"(p));
    return a;
}
__device__ __forceinline__ void cp16(uint32_t s, const void* g) {
    asm volatile("cp.async.cg.shared.global [%0], [%1], 16;" :: "r"(s), "l"(g));
}
__device__ __forceinline__ void cp_commit() {
    asm volatile("cp.async.commit_group;" ::: "memory");
}
__device__ __forceinline__ void ldsm4(uint32_t& r0, uint32_t& r1, uint32_t& r2, uint32_t& r3,
                                      uint32_t addr) {
    asm volatile("ldmatrix.sync.aligned.m8n8.x4.shared.b16 {%0,%1,%2,%3}, [%4];"
                 : "=r"(r0), "=r"(r1), "=r"(r2), "=r"(r3) : "r"(addr));
}
// fp16 inputs, fp32 accumulate
__device__ __forceinline__ void mma16816f(float* c, uint32_t a0, uint32_t a1, uint32_t a2,
                                          uint32_t a3, uint32_t b0, uint32_t b1) {
    asm volatile("mma.sync.aligned.m16n8k16.row.col.f32.f16.f16.f32 "
                 "{%0,%1,%2,%3}, {%4,%5,%6,%7}, {%8,%9}, {%0,%1,%2,%3};"
                 : "+f"(c[0]), "+f"(c[1]), "+f"(c[2]), "+f"(c[3])
                 : "r"(a0), "r"(a1), "r"(a2), "r"(a3), "r"(b0), "r"(b1));
}
// fp16 inputs, fp16 accumulate (corrections)
__device__ __forceinline__ void mma16816h(uint32_t* c, uint32_t a0, uint32_t a1, uint32_t a2,
                                          uint32_t a3, uint32_t b0, uint32_t b1) {
    asm volatile("mma.sync.aligned.m16n8k16.row.col.f16.f16.f16.f16 "
                 "{%0,%1}, {%2,%3,%4,%5}, {%6,%7}, {%0,%1};"
                 : "+r"(c[0]), "+r"(c[1])
                 : "r"(a0), "r"(a1), "r"(a2), "r"(a3), "r"(b0), "r"(b1));
}

// ---------------- Kernel 0: fp32 -> fp16 hi/lo split (lo scaled by 1024) -------
#define NA4 (GM * GK / 4)
#define NW4 (NW / 4)
__global__ void convert_kernel(const float* __restrict__ hs,
                               const float* __restrict__ k1w,
                               const float* __restrict__ v1w)
{
    const int i = blockIdx.x * 256 + threadIdx.x;
    const float* src;
    __half *dhi, *dlo;
    size_t off;
    if (i < NA4)            { src = hs;  dhi = g_Ahi;      dlo = g_Alo;      off = (size_t)i * 4; }
    else if (i < NA4 + NW4) { src = k1w; dhi = g_Whi;      dlo = g_Wlo;      off = (size_t)(i - NA4) * 4; }
    else                    { src = v1w; dhi = g_Whi + NW; dlo = g_Wlo + NW; off = (size_t)(i - NA4 - NW4) * 4; }

    const float4 v = *(const float4*)(src + off);
    __half h0 = __float2half(v.x);
    __half h1 = __float2half(v.y);
    __half h2 = __float2half(v.z);
    __half h3 = __float2half(v.w);
    __half l0 = __float2half((v.x - __half2float(h0)) * LOSCALE);
    __half l1 = __float2half((v.y - __half2float(h1)) * LOSCALE);
    __half l2 = __float2half((v.z - __half2float(h2)) * LOSCALE);
    __half l3 = __float2half((v.w - __half2float(h3)) * LOSCALE);
    *(__half2*)(dhi + off)     = __halves2half2(h0, h1);
    *(__half2*)(dhi + off + 2) = __halves2half2(h2, h3);
    *(__half2*)(dlo + off)     = __halves2half2(l0, l1);
    *(__half2*)(dlo + off + 2) = __halves2half2(l2, l3);
}

// ---------------- Kernel 1: fp16 split-3 GEMM ----------------------------------
// hi*hi in fp32 acc; (lo*hi + hi*lo) share one fp16 accumulator (x1024 scale),
// combined in the epilogue with 1/1024. Same tile/pipeline as R14.
#define RSTRIDE 80
#define TILEB   10240
#define STAGEB  (4 * TILEB)     // Ahi, Alo, Whi, Wlo
#define SMEMB   (2 * STAGEB)    // 81920
#define NCHUNK  24

__global__ void __launch_bounds__(256, 1)
gemm_mma_kernel(const float* __restrict__ b0v, const float* __restrict__ b1v,
                const float* __restrict__ rh)
{
    extern __shared__ __align__(16) char smem[];

    const int tid  = threadIdx.x;
    const int lane = tid & 31;
    const int wid  = tid >> 5;
    const int wr   = wid >> 2;          // 0..1 : 64-row slice
    const int wn   = wid & 3;           // 0..3 : 32-col slice
    const int bm   = blockIdx.x * 128;
    const int bn   = blockIdx.y * 128;
    const int z    = blockIdx.z;

    const uint32_t sb = smem_u32(smem);
    const __half* Wh = g_Whi + (size_t)z * NW;
    const __half* Wl = g_Wlo + (size_t)z * NW;

    const int gr = tid >> 1;
    const int gc = (tid & 1) * 2;

    auto load_chunk = [&](int kc, int buf) {
        const int k0 = kc * 32;
        const size_t go = (size_t)gr * GK + k0 + gc * 8;
        const __half* gah = g_Ahi + (size_t)bm * GK + go;
        const __half* gal = g_Alo + (size_t)bm * GK + go;
        const __half* gwh = Wh + (size_t)bn * GK + go;
        const __half* gwl = Wl + (size_t)bn * GK + go;
        const uint32_t d = sb + buf * STAGEB + gr * RSTRIDE + gc * 16;
        cp16(d,                 gah); cp16(d + 16,             gah + 8);
        cp16(d + TILEB,         gal); cp16(d + TILEB + 16,     gal + 8);
        cp16(d + 2 * TILEB,     gwh); cp16(d + 2 * TILEB + 16, gwh + 8);
        cp16(d + 3 * TILEB,     gwl); cp16(d + 3 * TILEB + 16, gwl + 8);
    };

    float acc[4][4][4];
    uint32_t cc[4][4][2];
    #pragma unroll
    for (int i = 0; i < 4; i++)
        #pragma unroll
        for (int j = 0; j < 4; j++) {
            #pragma unroll
            for (int q = 0; q < 4; q++) acc[i][j][q] = 0.f;
            cc[i][j][0] = 0u; cc[i][j][1] = 0u;
        }

    const uint32_t a_row  = wr * 64 + (lane & 15);
    const uint32_t a_koff = (lane >> 4) * 16;
    const uint32_t b_row  = wn * 32 + (lane & 7) + ((lane >> 4) & 1) * 8;
    const uint32_t b_koff = ((lane >> 3) & 1) * 16;

    load_chunk(0, 0);
    cp_commit();

    #pragma unroll 1
    for (int kc = 0; kc < NCHUNK; kc++) {
        const int buf = kc & 1;
        asm volatile("cp.async.wait_group 0;" ::: "memory");
        __syncthreads();
        if (kc + 1 < NCHUNK) { load_chunk(kc + 1, buf ^ 1); cp_commit(); }

        const uint32_t sAh = sb + buf * STAGEB;
        const uint32_t sAl = sAh + TILEB;
        const uint32_t sWh = sAh + 2 * TILEB;
        const uint32_t sWl = sAh + 3 * TILEB;

        #pragma unroll
        for (int ks = 0; ks < 2; ks++) {
            uint32_t ah[4][4], bh[4][2];
            #pragma unroll
            for (int i = 0; i < 4; i++)
                ldsm4(ah[i][0], ah[i][1], ah[i][2], ah[i][3],
                      sAh + (a_row + i * 16) * RSTRIDE + ks * 32 + a_koff);
            #pragma unroll
            for (int p = 0; p < 2; p++)
                ldsm4(bh[2*p][0], bh[2*p][1], bh[2*p+1][0], bh[2*p+1][1],
                      sWh + (b_row + p * 16) * RSTRIDE + ks * 32 + b_koff);
            #pragma unroll
            for (int i = 0; i < 4; i++)
                #pragma unroll
                for (int j = 0; j < 4; j++)
                    mma16816f(acc[i][j], ah[i][0], ah[i][1], ah[i][2], ah[i][3],
                              bh[j][0], bh[j][1]);

            {   // lo * hi  (Alo' x Whi) -> fp16 acc, bh still live
                uint32_t al[4][4];
                #pragma unroll
                for (int i = 0; i < 4; i++)
                    ldsm4(al[i][0], al[i][1], al[i][2], al[i][3],
                          sAl + (a_row + i * 16) * RSTRIDE + ks * 32 + a_koff);
                #pragma unroll
                for (int i = 0; i < 4; i++)
                    #pragma unroll
                    for (int j = 0; j < 4; j++)
                        mma16816h(cc[i][j], al[i][0], al[i][1], al[i][2], al[i][3],
                                  bh[j][0], bh[j][1]);
            }
            {   // hi * lo  (Ahi x Wlo') -> fp16 acc
                uint32_t bl[4][2];
                #pragma unroll
                for (int p = 0; p < 2; p++)
                    ldsm4(bl[2*p][0], bl[2*p][1], bl[2*p+1][0], bl[2*p+1][1],
                          sWl + (b_row + p * 16) * RSTRIDE + ks * 32 + b_koff);
                #pragma unroll
                for (int i = 0; i < 4; i++)
                    #pragma unroll
                    for (int j = 0; j < 4; j++)
                        mma16816h(cc[i][j], ah[i][0], ah[i][1], ah[i][2], ah[i][3],
                                  bl[j][0], bl[j][1]);
            }
        }
    }
    // fold corrections into fp32 acc
    #pragma unroll
    for (int i = 0; i < 4; i++)
        #pragma unroll
        for (int j = 0; j < 4; j++) {
            const float2 cr0 = __half22float2(*(const __half2*)&cc[i][j][0]); // {c0,c1}
            const float2 cr1 = __half22float2(*(const __half2*)&cc[i][j][1]); // {c2,c3}
            acc[i][j][0] += cr0.x * INV_LOSCALE;
            acc[i][j][1] += cr0.y * INV_LOSCALE;
            acc[i][j][2] += cr1.x * INV_LOSCALE;
            acc[i][j][3] += cr1.y * INV_LOSCALE;
        }
    __syncthreads();

    // ---------------- epilogues ----------------
    if (z == 0) {
        const float* bias = b0v;
        float pr[4][2];
        #pragma unroll
        for (int i = 0; i < 4; i++) { pr[i][0] = 0.f; pr[i][1] = 0.f; }

        #pragma unroll
        for (int j = 0; j < 4; j++) {
            const int cb = bn + wn * 32 + j * 8 + (lane & 3) * 2;
            const float bi0 = __ldg(bias + cb),  bi1 = __ldg(bias + cb + 1);
            const float w0  = __ldg(rh + cb),    w1  = __ldg(rh + cb + 1);
            #pragma unroll
            for (int i = 0; i < 4; i++) {
                const float* c = acc[i][j];
                pr[i][0] += fmaxf(c[0] + bi0, 0.f) * w0 + fmaxf(c[1] + bi1, 0.f) * w1;
                pr[i][1] += fmaxf(c[2] + bi0, 0.f) * w0 + fmaxf(c[3] + bi1, 0.f) * w1;
            }
        }
        float* spart = (float*)smem;       // [128][4]
        #pragma unroll
        for (int i = 0; i < 4; i++)
            #pragma unroll
            for (int hh = 0; hh < 2; hh++) {
                float v = pr[i][hh];
                v += __shfl_xor_sync(0xffffffffu, v, 1);
                v += __shfl_xor_sync(0xffffffffu, v, 2);
                if ((lane & 3) == 0) {
                    const int row = wr * 64 + i * 16 + (lane >> 2) + hh * 8;
                    spart[row * 4 + wn] = v;
                }
            }
        __syncthreads();
        const int row = tid >> 1, hs = tid & 1;
        const float s = spart[row * 4 + hs * 2] + spart[row * 4 + hs * 2 + 1];
        const int m = bm + row, b = m >> 9, l = m & 511;
        g_scores[(b * NH + blockIdx.y * 2 + hs) * LEN + l] = s;
    } else {
        const float* bias = b1v;
        #pragma unroll
        for (int i = 0; i < 4; i++) {
            const int r0 = bm + wr * 64 + i * 16 + (lane >> 2);
            #pragma unroll
            for (int j = 0; j < 4; j++) {
                const int col = bn + wn * 32 + j * 8 + (lane & 3) * 2;
                const float bi0 = __ldg(bias + col), bi1 = __ldg(bias + col + 1);
                const float* c = acc[i][j];
                const __half2 h0 = __floats2half2_rn(fmaxf(c[0] + bi0, 0.f),
                                                     fmaxf(c[1] + bi1, 0.f));
                const __half2 h1 = __floats2half2_rn(fmaxf(c[2] + bi0, 0.f),
                                                     fmaxf(c[3] + bi1, 0.f));
                *(__half2*)&g_V1h[(size_t)r0 * GN + col]       = h0;
                *(__half2*)&g_V1h[(size_t)(r0 + 8) * GN + col] = h1;
            }
        }
    }
}

// ---------------- Kernel 2: fully parallel scan (R11-proven) -------------------
#define BIGV (1 << 30)
__global__ void scan_kernel()
{
    const int bh = blockIdx.x;
    const int t  = threadIdx.x;           // = l
    const int lane = t & 31, w = t >> 5;

    __shared__ float red[16];
    __shared__ int evsm[LEN];
    __shared__ int c0s[LEN];
    __shared__ int c1s[LEN];
    __shared__ int pos[LEN + 1];
    __shared__ int wsum[16], wmax[16], wmin[16];

    const float x = g_scores[bh * LEN + t];

    float v = x;
    #pragma unroll
    for (int o = 16; o; o >>= 1) v = fmaxf(v, __shfl_xor_sync(0xffffffffu, v, o));
    if (lane == 0) red[w] = v;
    __syncthreads();
    float m = red[0];
    #pragma unroll
    for (int i = 1; i < 16; i++) m = fmaxf(m, red[i]);
    __syncthreads();

    const float e = expf(x - m);
    float sv = e;
    #pragma unroll
    for (int o = 16; o; o >>= 1) sv += __shfl_xor_sync(0xffffffffu, sv, o);
    if (lane == 0) red[w] = sv;
    __syncthreads();
    float s = 0.f;
    #pragma unroll
    for (int i = 0; i < 16; i++) s += red[i];

    const float p = e / s + expf(-m);
    const int ev = (p > (1.5f / 512.0f)) ? 1 : 0;
    evsm[t] = ev;
    __syncthreads();

    int r  = (t >= 1) ? ev : 0;           // rank: events in 1..l
    int m0 = ev ? t : -1;                 // prefix max of event index
    #pragma unroll
    for (int o = 1; o < 32; o <<= 1) {
        const int nr = __shfl_up_sync(0xffffffffu, r, o);
        const int nm = __shfl_up_sync(0xffffffffu, m0, o);
        if (lane >= o) { r += nr; m0 = (nm > m0) ? nm : m0; }
    }
    const int rolled = (t < LEN - 1) ? evsm[t + 1] : evsm[0];
    int m1 = rolled ? t : BIGV;           // suffix min of rolled-event index
    #pragma unroll
    for (int o = 1; o < 32; o <<= 1) {
        const int nm = __shfl_down_sync(0xffffffffu, m1, o);
        if (lane + o < 32) m1 = (nm < m1) ? nm : m1;
    }
    if (lane == 31) { wsum[w] = r; wmax[w] = m0; }
    if (lane == 0)  { wmin[w] = m1; }
    __syncthreads();

    int sumoff = 0, maxoff = -1, minoff = BIGV;
    #pragma unroll
    for (int i = 0; i < 16; i++) {
        if (i < w) {
            sumoff += wsum[i];
            maxoff = (wmax[i] > maxoff) ? wmax[i] : maxoff;
        }
        if (i > w) minoff = (wmin[i] < minoff) ? wmin[i] : minoff;
    }
    const int rank = r + sumoff;
    const int M0 = (maxoff > m0) ? maxoff : m0;
    const int M1 = (minoff < m1) ? minoff : m1;
    const int c0 = (M0 >= 0) ? M0 : t;
    int c1 = (M1 < BIGV) ? (M1 + 1) : (t + 1);
    if (t == 0) c1 = 0;
    c0s[t] = c0;
    c1s[t] = c1;
    if (t >= 1 && ev) pos[rank] = t;
    __syncthreads();

    int vals[16];
    #pragma unroll
    for (int j = 0; j < 8; j++) {
        const int k = rank - j;
        int f = 0, b = 0;
        if (k >= 1) { const int pp = pos[k]; f = c0s[pp - 1]; b = c1s[pp - 1]; }
        vals[2 * j]     = (f > LEN - 1) ? LEN - 1 : f;
        vals[2 * j + 1] = (b > LEN - 1) ? LEN - 1 : b;
    }
    int4* dst = (int4*)(g_idx + (size_t)bh * LEN * R2V + t * R2V);
    dst[0] = make_int4(vals[0],  vals[1],  vals[2],  vals[3]);
    dst[1] = make_int4(vals[4],  vals[5],  vals[6],  vals[7]);
    dst[2] = make_int4(vals[8],  vals[9],  vals[10], vals[11]);
    dst[3] = make_int4(vals[12], vals[13], vals[14], vals[15]);
}

// ---------------- Kernel 3: gather 16 fp16 V rows + weighted sum ---------------
__global__ void gather_kernel(const float* __restrict__ w, float* __restrict__ out)
{
    const int b = blockIdx.z;
    const int h = blockIdx.y;
    const int lgrp = threadIdx.x >> 4;
    const int l = blockIdx.x * 16 + lgrp;
    const int j = threadIdx.x & 15;

    __shared__ float ws[R2V];
    if (threadIdx.x < R2V) ws[threadIdx.x] = w[h * R2V + threadIdx.x];
    __syncthreads();

    const int myidx = g_idx[(((size_t)(b * NH + h) * LEN + l) * R2V) + j];
    const __half* Vb = g_V1h + (size_t)b * LEN * GN + h * HD;

    float4 acc = make_float4(0.f, 0.f, 0.f, 0.f);
    #pragma unroll
    for (int r = 0; r < R2V; r++) {
        const int src = (threadIdx.x & 16) + r;
        const int rowi = __shfl_sync(0xffffffffu, myidx, src, 32);
        const float wr = ws[r];
        const uint2 raw = *(const uint2*)(Vb + (size_t)rowi * GN + j * 4);
        const float2 va = __half22float2(*reinterpret_cast<const __half2*>(&raw.x));
        const float2 vb = __half22float2(*reinterpret_cast<const __half2*>(&raw.y));
        acc.x += wr * va.x; acc.y += wr * va.y;
        acc.z += wr * vb.x; acc.w += wr * vb.y;
    }
    float* op = out + (((size_t)(b * LEN + l) * NH + h) * HD) + j * 4;
    *(float4*)op = acc;
}

// ---------------- launch -------------------------------------------------------
extern "C" void kernel_launch(void* const* d_in, const int* in_sizes, int n_in,
                              void* d_out, int out_size)
{
    const float* hs  = (const float*)d_in[0];
    const float* K1w = (const float*)d_in[1];
    const float* K1b = (const float*)d_in[2];
    const float* V1w = (const float*)d_in[3];
    const float* V1b = (const float*)d_in[4];
    const float* rh  = (const float*)d_in[5];
    const float* bw  = (const float*)d_in[6];
    float* out = (float*)d_out;

    cudaFuncSetAttribute(gemm_mma_kernel,
                         cudaFuncAttributeMaxDynamicSharedMemorySize, SMEMB);

    convert_kernel<<<(NA4 + 2 * NW4) / 256, 256>>>(hs, K1w, V1w);

    dim3 gg(GM / 128, GN / 128, 2);                       // 64 x 6 x 2
    gemm_mma_kernel<<<gg, 256, SMEMB>>>(K1b, V1b, rh);

    scan_kernel<<<BSZ * NH, 512>>>();

    dim3 g4(LEN / 16, NH, BSZ);
    gather_kernel<<<g4, 256>>>(bw, out);
}

// round 16
// speedup vs baseline: 1.3290x; 1.3290x over previous
#include <cuda_runtime.h>
#include <cuda_fp16.h>
#include <math.h>
#include <stdint.h>

// Problem dims
#define BSZ 16
#define LEN 512
#define HIDD 768
#define NH 12
#define HD 64
#define R2V 16
#define GM (BSZ*LEN)          // 8192 rows
#define GN HIDD
#define GK HIDD
#define NW (768*768)

// ---------------- scratch (device globals) ------------------------------------
__device__ __align__(16) __half g_V1h[(size_t)GM * GN];    // fp16 V1 (relu >= 0)
__device__ __align__(16) __half g_Ahi[(size_t)GM * GK];
__device__ __align__(16) __half g_Alo[(size_t)GM * GK];    // a - hi (unscaled)
__device__ __align__(16) __half g_Whi[2 * NW];
__device__ __align__(16) __half g_Wlo[2 * NW];             // w - hi (unscaled)
__device__ float g_scores[BSZ * NH * LEN];
__device__ int   g_idx[BSZ * NH * LEN * R2V];

// ---------------- PTX helpers (sm_80-baseline only) ----------------------------
__device__ __forceinline__ uint32_t smem_u32(const void* p) {
    uint32_t a;
    asm("{ .reg .u64 t; cvta.to.shared.u64 t, %1; cvt.u32.u64 %0, t; }" : "=r"(a) : "l"(p));
    return a;
}
__device__ __forceinline__ void cp16(uint32_t s, const void* g) {
    asm volatile("cp.async.cg.shared.global [%0], [%1], 16;" :: "r"(s), "l"(g));
}
__device__ __forceinline__ void cp_commit() {
    asm volatile("cp.async.commit_group;" ::: "memory");
}
__device__ __forceinline__ void ldsm4(uint32_t& r0, uint32_t& r1, uint32_t& r2, uint32_t& r3,
                                      uint32_t addr) {
    asm volatile("ldmatrix.sync.aligned.m8n8.x4.shared.b16 {%0,%1,%2,%3}, [%4];"
                 : "=r"(r0), "=r"(r1), "=r"(r2), "=r"(r3) : "r"(addr));
}
// fp16 inputs, fp32 accumulate
__device__ __forceinline__ void mma16816(float* c, uint32_t a0, uint32_t a1, uint32_t a2,
                                         uint32_t a3, uint32_t b0, uint32_t b1) {
    asm volatile("mma.sync.aligned.m16n8k16.row.col.f32.f16.f16.f32 "
                 "{%0,%1,%2,%3}, {%4,%5,%6,%7}, {%8,%9}, {%0,%1,%2,%3};"
                 : "+f"(c[0]), "+f"(c[1]), "+f"(c[2]), "+f"(c[3])
                 : "r"(a0), "r"(a1), "r"(a2), "r"(a3), "r"(b0), "r"(b1));
}

// ---------------- Kernel 0: fp32 -> fp16 hi/lo split ---------------------------
#define NA4 (GM * GK / 4)
#define NW4 (NW / 4)
__global__ void convert_kernel(const float* __restrict__ hs,
                               const float* __restrict__ k1w,
                               const float* __restrict__ v1w)
{
    const int i = blockIdx.x * 256 + threadIdx.x;
    const float* src;
    __half *dhi, *dlo;
    size_t off;
    if (i < NA4)            { src = hs;  dhi = g_Ahi;      dlo = g_Alo;      off = (size_t)i * 4; }
    else if (i < NA4 + NW4) { src = k1w; dhi = g_Whi;      dlo = g_Wlo;      off = (size_t)(i - NA4) * 4; }
    else                    { src = v1w; dhi = g_Whi + NW; dlo = g_Wlo + NW; off = (size_t)(i - NA4 - NW4) * 4; }

    const float4 v = *(const float4*)(src + off);
    __half h0 = __float2half(v.x);
    __half h1 = __float2half(v.y);
    __half h2 = __float2half(v.z);
    __half h3 = __float2half(v.w);
    __half l0 = __float2half(v.x - __half2float(h0));
    __half l1 = __float2half(v.y - __half2float(h1));
    __half l2 = __float2half(v.z - __half2float(h2));
    __half l3 = __float2half(v.w - __half2float(h3));
    *(__half2*)(dhi + off)     = __halves2half2(h0, h1);
    *(__half2*)(dhi + off + 2) = __halves2half2(h2, h3);
    *(__half2*)(dlo + off)     = __halves2half2(l0, l1);
    *(__half2*)(dlo + off + 2) = __halves2half2(l2, l3);
}

// ---------------- Kernel 1: fp16 split GEMM, fused per-chunk phases ------------
// z==0 (K1->scores): 3 terms (hi*hi + lo*hi + hi*lo) — event threshold needs
//   ~1e-6 score accuracy.
// z==1 (V1): 2 terms (hi*hi + lo*hi) — dropped hi*lo is ~ eps_fp16-sized,
//   well under the fp16-storage error already present; Wlo not even loaded.
// Same 128x128 tile, 24 chunks, 2-stage cp.async, all-fp32 accumulators, occ 2.
#define RSTRIDE 80
#define TILEB   10240
#define STAGEB  (4 * TILEB)     // Ahi, Alo, Whi, Wlo
#define SMEMB   (2 * STAGEB)    // 81920
#define NCHUNK  24

__global__ void __launch_bounds__(256, 2)
gemm_mma_kernel(const float* __restrict__ b0v, const float* __restrict__ b1v,
                const float* __restrict__ rh)
{
    extern __shared__ __align__(16) char smem[];

    const int tid  = threadIdx.x;
    const int lane = tid & 31;
    const int wid  = tid >> 5;
    const int wr   = wid >> 2;          // 0..1 : 64-row slice
    const int wn   = wid & 3;           // 0..3 : 32-col slice
    const int bm   = blockIdx.x * 128;
    const int bn   = blockIdx.y * 128;
    const int z    = blockIdx.z;

    const uint32_t sb = smem_u32(smem);
    const __half* Wh = g_Whi + (size_t)z * NW;
    const __half* Wl = g_Wlo + (size_t)z * NW;

    const int gr = tid >> 1;
    const int gc = (tid & 1) * 2;

    auto load_chunk = [&](int kc, int buf) {
        const int k0 = kc * 32;
        const size_t go = (size_t)gr * GK + k0 + gc * 8;
        const __half* gah = g_Ahi + (size_t)bm * GK + go;
        const __half* gal = g_Alo + (size_t)bm * GK + go;
        const __half* gwh = Wh + (size_t)bn * GK + go;
        const uint32_t d = sb + buf * STAGEB + gr * RSTRIDE + gc * 16;
        cp16(d,                 gah); cp16(d + 16,             gah + 8);
        cp16(d + TILEB,         gal); cp16(d + TILEB + 16,     gal + 8);
        cp16(d + 2 * TILEB,     gwh); cp16(d + 2 * TILEB + 16, gwh + 8);
        if (z == 0) {
            const __half* gwl = Wl + (size_t)bn * GK + go;
            cp16(d + 3 * TILEB,     gwl);
            cp16(d + 3 * TILEB + 16, gwl + 8);
        }
    };

    float acc[4][4][4];
    #pragma unroll
    for (int i = 0; i < 4; i++)
        #pragma unroll
        for (int j = 0; j < 4; j++)
            #pragma unroll
            for (int q = 0; q < 4; q++) acc[i][j][q] = 0.f;

    const uint32_t a_row  = wr * 64 + (lane & 15);
    const uint32_t a_koff = (lane >> 4) * 16;
    const uint32_t b_row  = wn * 32 + (lane & 7) + ((lane >> 4) & 1) * 8;
    const uint32_t b_koff = ((lane >> 3) & 1) * 16;

    load_chunk(0, 0);
    cp_commit();

    #pragma unroll 1
    for (int kc = 0; kc < NCHUNK; kc++) {
        const int buf = kc & 1;
        asm volatile("cp.async.wait_group 0;" ::: "memory");
        __syncthreads();
        if (kc + 1 < NCHUNK) { load_chunk(kc + 1, buf ^ 1); cp_commit(); }

        const uint32_t sAh = sb + buf * STAGEB;
        const uint32_t sAl = sAh + TILEB;
        const uint32_t sWh = sAh + 2 * TILEB;
        const uint32_t sWl = sAh + 3 * TILEB;

        #pragma unroll
        for (int ks = 0; ks < 2; ks++) {
            uint32_t ah[4][4], bh[4][2];
            #pragma unroll
            for (int i = 0; i < 4; i++)
                ldsm4(ah[i][0], ah[i][1], ah[i][2], ah[i][3],
                      sAh + (a_row + i * 16) * RSTRIDE + ks * 32 + a_koff);
            #pragma unroll
            for (int p = 0; p < 2; p++)
                ldsm4(bh[2*p][0], bh[2*p][1], bh[2*p+1][0], bh[2*p+1][1],
                      sWh + (b_row + p * 16) * RSTRIDE + ks * 32 + b_koff);
            #pragma unroll
            for (int i = 0; i < 4; i++)
                #pragma unroll
                for (int j = 0; j < 4; j++)
                    mma16816(acc[i][j], ah[i][0], ah[i][1], ah[i][2], ah[i][3],
                             bh[j][0], bh[j][1]);

            {   // lo * hi  (Alo x Whi), bh still live — both GEMMs
                uint32_t al[4][4];
                #pragma unroll
                for (int i = 0; i < 4; i++)
                    ldsm4(al[i][0], al[i][1], al[i][2], al[i][3],
                          sAl + (a_row + i * 16) * RSTRIDE + ks * 32 + a_koff);
                #pragma unroll
                for (int i = 0; i < 4; i++)
                    #pragma unroll
                    for (int j = 0; j < 4; j++)
                        mma16816(acc[i][j], al[i][0], al[i][1], al[i][2], al[i][3],
                                 bh[j][0], bh[j][1]);
            }
            if (z == 0) {   // hi * lo  (Ahi x Wlo) — scores only
                uint32_t bl[4][2];
                #pragma unroll
                for (int p = 0; p < 2; p++)
                    ldsm4(bl[2*p][0], bl[2*p][1], bl[2*p+1][0], bl[2*p+1][1],
                          sWl + (b_row + p * 16) * RSTRIDE + ks * 32 + b_koff);
                #pragma unroll
                for (int i = 0; i < 4; i++)
                    #pragma unroll
                    for (int j = 0; j < 4; j++)
                        mma16816(acc[i][j], ah[i][0], ah[i][1], ah[i][2], ah[i][3],
                                 bl[j][0], bl[j][1]);
            }
        }
    }
    __syncthreads();

    // ---------------- epilogues ----------------
    if (z == 0) {
        const float* bias = b0v;
        float pr[4][2];
        #pragma unroll
        for (int i = 0; i < 4; i++) { pr[i][0] = 0.f; pr[i][1] = 0.f; }

        #pragma unroll
        for (int j = 0; j < 4; j++) {
            const int cb = bn + wn * 32 + j * 8 + (lane & 3) * 2;
            const float bi0 = __ldg(bias + cb),  bi1 = __ldg(bias + cb + 1);
            const float w0  = __ldg(rh + cb),    w1  = __ldg(rh + cb + 1);
            #pragma unroll
            for (int i = 0; i < 4; i++) {
                const float* c = acc[i][j];
                pr[i][0] += fmaxf(c[0] + bi0, 0.f) * w0 + fmaxf(c[1] + bi1, 0.f) * w1;
                pr[i][1] += fmaxf(c[2] + bi0, 0.f) * w0 + fmaxf(c[3] + bi1, 0.f) * w1;
            }
        }
        float* spart = (float*)smem;       // [128][4]
        #pragma unroll
        for (int i = 0; i < 4; i++)
            #pragma unroll
            for (int hh = 0; hh < 2; hh++) {
                float v = pr[i][hh];
                v += __shfl_xor_sync(0xffffffffu, v, 1);
                v += __shfl_xor_sync(0xffffffffu, v, 2);
                if ((lane & 3) == 0) {
                    const int row = wr * 64 + i * 16 + (lane >> 2) + hh * 8;
                    spart[row * 4 + wn] = v;
                }
            }
        __syncthreads();
        const int row = tid >> 1, hs = tid & 1;
        const float s = spart[row * 4 + hs * 2] + spart[row * 4 + hs * 2 + 1];
        const int m = bm + row, b = m >> 9, l = m & 511;
        g_scores[(b * NH + blockIdx.y * 2 + hs) * LEN + l] = s;
    } else {
        const float* bias = b1v;
        #pragma unroll
        for (int i = 0; i < 4; i++) {
            const int r0 = bm + wr * 64 + i * 16 + (lane >> 2);
            #pragma unroll
            for (int j = 0; j < 4; j++) {
                const int col = bn + wn * 32 + j * 8 + (lane & 3) * 2;
                const float bi0 = __ldg(bias + col), bi1 = __ldg(bias + col + 1);
                const float* c = acc[i][j];
                const __half2 h0 = __floats2half2_rn(fmaxf(c[0] + bi0, 0.f),
                                                     fmaxf(c[1] + bi1, 0.f));
                const __half2 h1 = __floats2half2_rn(fmaxf(c[2] + bi0, 0.f),
                                                     fmaxf(c[3] + bi1, 0.f));
                *(__half2*)&g_V1h[(size_t)r0 * GN + col]       = h0;
                *(__half2*)&g_V1h[(size_t)(r0 + 8) * GN + col] = h1;
            }
        }
    }
}

// ---------------- Kernel 2: fully parallel scan (R11-proven) -------------------
#define BIGV (1 << 30)
__global__ void scan_kernel()
{
    const int bh = blockIdx.x;
    const int t  = threadIdx.x;           // = l
    const int lane = t & 31, w = t >> 5;

    __shared__ float red[16];
    __shared__ int evsm[LEN];
    __shared__ int c0s[LEN];
    __shared__ int c1s[LEN];
    __shared__ int pos[LEN + 1];
    __shared__ int wsum[16], wmax[16], wmin[16];

    const float x = g_scores[bh * LEN + t];

    float v = x;
    #pragma unroll
    for (int o = 16; o; o >>= 1) v = fmaxf(v, __shfl_xor_sync(0xffffffffu, v, o));
    if (lane == 0) red[w] = v;
    __syncthreads();
    float m = red[0];
    #pragma unroll
    for (int i = 1; i < 16; i++) m = fmaxf(m, red[i]);
    __syncthreads();

    const float e = expf(x - m);
    float sv = e;
    #pragma unroll
    for (int o = 16; o; o >>= 1) sv += __shfl_xor_sync(0xffffffffu, sv, o);
    if (lane == 0) red[w] = sv;
    __syncthreads();
    float s = 0.f;
    #pragma unroll
    for (int i = 0; i < 16; i++) s += red[i];

    const float p = e / s + expf(-m);
    const int ev = (p > (1.5f / 512.0f)) ? 1 : 0;
    evsm[t] = ev;
    __syncthreads();

    int r  = (t >= 1) ? ev : 0;           // rank: events in 1..l
    int m0 = ev ? t : -1;                 // prefix max of event index
    #pragma unroll
    for (int o = 1; o < 32; o <<= 1) {
        const int nr = __shfl_up_sync(0xffffffffu, r, o);
        const int nm = __shfl_up_sync(0xffffffffu, m0, o);
        if (lane >= o) { r += nr; m0 = (nm > m0) ? nm : m0; }
    }
    const int rolled = (t < LEN - 1) ? evsm[t + 1] : evsm[0];
    int m1 = rolled ? t : BIGV;           // suffix min of rolled-event index
    #pragma unroll
    for (int o = 1; o < 32; o <<= 1) {
        const int nm = __shfl_down_sync(0xffffffffu, m1, o);
        if (lane + o < 32) m1 = (nm < m1) ? nm : m1;
    }
    if (lane == 31) { wsum[w] = r; wmax[w] = m0; }
    if (lane == 0)  { wmin[w] = m1; }
    __syncthreads();

    int sumoff = 0, maxoff = -1, minoff = BIGV;
    #pragma unroll
    for (int i = 0; i < 16; i++) {
        if (i < w) {
            sumoff += wsum[i];
            maxoff = (wmax[i] > maxoff) ? wmax[i] : maxoff;
        }
        if (i > w) minoff = (wmin[i] < minoff) ? wmin[i] : minoff;
    }
    const int rank = r + sumoff;
    const int M0 = (maxoff > m0) ? maxoff : m0;
    const int M1 = (minoff < m1) ? minoff : m1;
    const int c0 = (M0 >= 0) ? M0 : t;
    int c1 = (M1 < BIGV) ? (M1 + 1) : (t + 1);
    if (t == 0) c1 = 0;
    c0s[t] = c0;
    c1s[t] = c1;
    if (t >= 1 && ev) pos[rank] = t;
    __syncthreads();

    int vals[16];
    #pragma unroll
    for (int j = 0; j < 8; j++) {
        const int k = rank - j;
        int f = 0, b = 0;
        if (k >= 1) { const int pp = pos[k]; f = c0s[pp - 1]; b = c1s[pp - 1]; }
        vals[2 * j]     = (f > LEN - 1) ? LEN - 1 : f;
        vals[2 * j + 1] = (b > LEN - 1) ? LEN - 1 : b;
    }
    int4* dst = (int4*)(g_idx + (size_t)bh * LEN * R2V + t * R2V);
    dst[0] = make_int4(vals[0],  vals[1],  vals[2],  vals[3]);
    dst[1] = make_int4(vals[4],  vals[5],  vals[6],  vals[7]);
    dst[2] = make_int4(vals[8],  vals[9],  vals[10], vals[11]);
    dst[3] = make_int4(vals[12], vals[13], vals[14], vals[15]);
}

// ---------------- Kernel 3: gather 16 fp16 V rows + weighted sum ---------------
__global__ void gather_kernel(const float* __restrict__ w, float* __restrict__ out)
{
    const int b = blockIdx.z;
    const int h = blockIdx.y;
    const int lgrp = threadIdx.x >> 4;
    const int l = blockIdx.x * 16 + lgrp;
    const int j = threadIdx.x & 15;

    __shared__ float ws[R2V];
    if (threadIdx.x < R2V) ws[threadIdx.x] = w[h * R2V + threadIdx.x];
    __syncthreads();

    const int myidx = g_idx[(((size_t)(b * NH + h) * LEN + l) * R2V) + j];
    const __half* Vb = g_V1h + (size_t)b * LEN * GN + h * HD;

    float4 acc = make_float4(0.f, 0.f, 0.f, 0.f);
    #pragma unroll
    for (int r = 0; r < R2V; r++) {
        const int src = (threadIdx.x & 16) + r;
        const int rowi = __shfl_sync(0xffffffffu, myidx, src, 32);
        const float wr = ws[r];
        const uint2 raw = *(const uint2*)(Vb + (size_t)rowi * GN + j * 4);
        const float2 va = __half22float2(*reinterpret_cast<const __half2*>(&raw.x));
        const float2 vb = __half22float2(*reinterpret_cast<const __half2*>(&raw.y));
        acc.x += wr * va.x; acc.y += wr * va.y;
        acc.z += wr * vb.x; acc.w += wr * vb.y;
    }
    float* op = out + (((size_t)(b * LEN + l) * NH + h) * HD) + j * 4;
    *(float4*)op = acc;
}

// ---------------- launch -------------------------------------------------------
extern "C" void kernel_launch(void* const* d_in, const int* in_sizes, int n_in,
                              void* d_out, int out_size)
{
    const float* hs  = (const float*)d_in[0];
    const float* K1w = (const float*)d_in[1];
    const float* K1b = (const float*)d_in[2];
    const float* V1w = (const float*)d_in[3];
    const float* V1b = (const float*)d_in[4];
    const float* rh  = (const float*)d_in[5];
    const float* bw  = (const float*)d_in[6];
    float* out = (float*)d_out;

    cudaFuncSetAttribute(gemm_mma_kernel,
                         cudaFuncAttributeMaxDynamicSharedMemorySize, SMEMB);

    convert_kernel<<<(NA4 + 2 * NW4) / 256, 256>>>(hs, K1w, V1w);

    dim3 gg(GM / 128, GN / 128, 2);                       // 64 x 6 x 2
    gemm_mma_kernel<<<gg, 256, SMEMB>>>(K1b, V1b, rh);

    scan_kernel<<<BSZ * NH, 512>>>();

    dim3 g4(LEN / 16, NH, BSZ);
    gather_kernel<<<g4, 256>>>(bw, out);
}

// round 17
// speedup vs baseline: 1.6658x; 1.2534x over previous
#include <cuda_runtime.h>
#include <cuda_fp16.h>
#include <math.h>
#include <stdint.h>

// Problem dims
#define BSZ 16
#define LEN 512
#define HIDD 768
#define NH 12
#define HD 64
#define R2V 16
#define GM (BSZ*LEN)          // 8192 rows
#define GN HIDD
#define GK HIDD
#define NW (768*768)

// ---------------- scratch (device globals) ------------------------------------
__device__ __align__(16) __half g_V1h[(size_t)GM * GN];    // fp16 V1 (relu >= 0)
__device__ __align__(16) __half g_Ahi[(size_t)GM * GK];
__device__ __align__(16) __half g_Alo[(size_t)GM * GK];    // a - hi (unscaled)
__device__ __align__(16) __half g_Whi[2 * NW];
__device__ __align__(16) __half g_Wlo[2 * NW];             // w - hi (unscaled)
__device__ float g_scores[BSZ * NH * LEN];
__device__ int   g_idx[BSZ * NH * LEN * R2V];

// ---------------- PTX helpers (sm_80-baseline only) ----------------------------
__device__ __forceinline__ uint32_t smem_u32(const void* p) {
    uint32_t a;
    asm("{ .reg .u64 t; cvta.to.shared.u64 t, %1; cvt.u32.u64 %0, t; }" : "=r"(a) : "l"(p));
    return a;
}
__device__ __forceinline__ void cp16(uint32_t s, const void* g) {
    asm volatile("cp.async.cg.shared.global [%0], [%1], 16;" :: "r"(s), "l"(g));
}
__device__ __forceinline__ void cp_commit() {
    asm volatile("cp.async.commit_group;" ::: "memory");
}
__device__ __forceinline__ void ldsm4(uint32_t& r0, uint32_t& r1, uint32_t& r2, uint32_t& r3,
                                      uint32_t addr) {
    asm volatile("ldmatrix.sync.aligned.m8n8.x4.shared.b16 {%0,%1,%2,%3}, [%4];"
                 : "=r"(r0), "=r"(r1), "=r"(r2), "=r"(r3) : "r"(addr));
}
// fp16 inputs, fp32 accumulate
__device__ __forceinline__ void mma16816(float* c, uint32_t a0, uint32_t a1, uint32_t a2,
                                         uint32_t a3, uint32_t b0, uint32_t b1) {
    asm volatile("mma.sync.aligned.m16n8k16.row.col.f32.f16.f16.f32 "
                 "{%0,%1,%2,%3}, {%4,%5,%6,%7}, {%8,%9}, {%0,%1,%2,%3};"
                 : "+f"(c[0]), "+f"(c[1]), "+f"(c[2]), "+f"(c[3])
                 : "r"(a0), "r"(a1), "r"(a2), "r"(a3), "r"(b0), "r"(b1));
}

// ---------------- Kernel 0: fp32 -> fp16 hi/lo split ---------------------------
#define NA4 (GM * GK / 4)
#define NW4 (NW / 4)
__global__ void convert_kernel(const float* __restrict__ hs,
                               const float* __restrict__ k1w,
                               const float* __restrict__ v1w)
{
    const int i = blockIdx.x * 256 + threadIdx.x;
    const float* src;
    __half *dhi, *dlo;
    size_t off;
    if (i < NA4)            { src = hs;  dhi = g_Ahi;      dlo = g_Alo;      off = (size_t)i * 4; }
    else if (i < NA4 + NW4) { src = k1w; dhi = g_Whi;      dlo = g_Wlo;      off = (size_t)(i - NA4) * 4; }
    else                    { src = v1w; dhi = g_Whi + NW; dlo = g_Wlo + NW; off = (size_t)(i - NA4 - NW4) * 4; }

    const float4 v = *(const float4*)(src + off);
    __half h0 = __float2half(v.x);
    __half h1 = __float2half(v.y);
    __half h2 = __float2half(v.z);
    __half h3 = __float2half(v.w);
    __half l0 = __float2half(v.x - __half2float(h0));
    __half l1 = __float2half(v.y - __half2float(h1));
    __half l2 = __float2half(v.z - __half2float(h2));
    __half l3 = __float2half(v.w - __half2float(h3));
    *(__half2*)(dhi + off)     = __halves2half2(h0, h1);
    *(__half2*)(dhi + off + 2) = __halves2half2(h2, h3);
    *(__half2*)(dlo + off)     = __halves2half2(l0, l1);
    *(__half2*)(dlo + off + 2) = __halves2half2(l2, l3);
}

// ---------------- Kernel 1: fp16 split GEMM, fused per-chunk phases ------------
// z==0 (K1->scores): 3 terms (hi*hi + lo*hi + hi*lo) — event threshold needs
//   ~1e-6 score accuracy.
// z==1 (V1): 1 term (hi*hi) — both dropped terms are eps_fp16-sized; with the
//   fp16 V1 storage already at that scale the total stays ~2e-4 << 1e-3.
//   Only Ahi + Whi tiles are loaded for z==1.
// Same 128x128 tile, 24 chunks, 2-stage cp.async, fp32 accumulators, occ 2.
#define RSTRIDE 80
#define TILEB   10240
#define STAGEB  (4 * TILEB)     // Ahi, Alo, Whi, Wlo
#define SMEMB   (2 * STAGEB)    // 81920
#define NCHUNK  24

__global__ void __launch_bounds__(256, 2)
gemm_mma_kernel(const float* __restrict__ b0v, const float* __restrict__ b1v,
                const float* __restrict__ rh)
{
    extern __shared__ __align__(16) char smem[];

    const int tid  = threadIdx.x;
    const int lane = tid & 31;
    const int wid  = tid >> 5;
    const int wr   = wid >> 2;          // 0..1 : 64-row slice
    const int wn   = wid & 3;           // 0..3 : 32-col slice
    const int bm   = blockIdx.x * 128;
    const int bn   = blockIdx.y * 128;
    const int z    = blockIdx.z;

    const uint32_t sb = smem_u32(smem);
    const __half* Wh = g_Whi + (size_t)z * NW;
    const __half* Wl = g_Wlo + (size_t)z * NW;

    const int gr = tid >> 1;
    const int gc = (tid & 1) * 2;

    auto load_chunk = [&](int kc, int buf) {
        const int k0 = kc * 32;
        const size_t go = (size_t)gr * GK + k0 + gc * 8;
        const __half* gah = g_Ahi + (size_t)bm * GK + go;
        const __half* gwh = Wh + (size_t)bn * GK + go;
        const uint32_t d = sb + buf * STAGEB + gr * RSTRIDE + gc * 16;
        cp16(d,                 gah); cp16(d + 16,             gah + 8);
        cp16(d + 2 * TILEB,     gwh); cp16(d + 2 * TILEB + 16, gwh + 8);
        if (z == 0) {
            const __half* gal = g_Alo + (size_t)bm * GK + go;
            const __half* gwl = Wl + (size_t)bn * GK + go;
            cp16(d + TILEB,          gal);
            cp16(d + TILEB + 16,     gal + 8);
            cp16(d + 3 * TILEB,      gwl);
            cp16(d + 3 * TILEB + 16, gwl + 8);
        }
    };

    float acc[4][4][4];
    #pragma unroll
    for (int i = 0; i < 4; i++)
        #pragma unroll
        for (int j = 0; j < 4; j++)
            #pragma unroll
            for (int q = 0; q < 4; q++) acc[i][j][q] = 0.f;

    const uint32_t a_row  = wr * 64 + (lane & 15);
    const uint32_t a_koff = (lane >> 4) * 16;
    const uint32_t b_row  = wn * 32 + (lane & 7) + ((lane >> 4) & 1) * 8;
    const uint32_t b_koff = ((lane >> 3) & 1) * 16;

    load_chunk(0, 0);
    cp_commit();

    #pragma unroll 1
    for (int kc = 0; kc < NCHUNK; kc++) {
        const int buf = kc & 1;
        asm volatile("cp.async.wait_group 0;" ::: "memory");
        __syncthreads();
        if (kc + 1 < NCHUNK) { load_chunk(kc + 1, buf ^ 1); cp_commit(); }

        const uint32_t sAh = sb + buf * STAGEB;
        const uint32_t sAl = sAh + TILEB;
        const uint32_t sWh = sAh + 2 * TILEB;
        const uint32_t sWl = sAh + 3 * TILEB;

        #pragma unroll
        for (int ks = 0; ks < 2; ks++) {
            uint32_t ah[4][4], bh[4][2];
            #pragma unroll
            for (int i = 0; i < 4; i++)
                ldsm4(ah[i][0], ah[i][1], ah[i][2], ah[i][3],
                      sAh + (a_row + i * 16) * RSTRIDE + ks * 32 + a_koff);
            #pragma unroll
            for (int p = 0; p < 2; p++)
                ldsm4(bh[2*p][0], bh[2*p][1], bh[2*p+1][0], bh[2*p+1][1],
                      sWh + (b_row + p * 16) * RSTRIDE + ks * 32 + b_koff);
            #pragma unroll
            for (int i = 0; i < 4; i++)
                #pragma unroll
                for (int j = 0; j < 4; j++)
                    mma16816(acc[i][j], ah[i][0], ah[i][1], ah[i][2], ah[i][3],
                             bh[j][0], bh[j][1]);

            if (z == 0) {   // lo * hi  (Alo x Whi), bh still live — scores only
                uint32_t al[4][4];
                #pragma unroll
                for (int i = 0; i < 4; i++)
                    ldsm4(al[i][0], al[i][1], al[i][2], al[i][3],
                          sAl + (a_row + i * 16) * RSTRIDE + ks * 32 + a_koff);
                #pragma unroll
                for (int i = 0; i < 4; i++)
                    #pragma unroll
                    for (int j = 0; j < 4; j++)
                        mma16816(acc[i][j], al[i][0], al[i][1], al[i][2], al[i][3],
                                 bh[j][0], bh[j][1]);
            }
            if (z == 0) {   // hi * lo  (Ahi x Wlo) — scores only
                uint32_t bl[4][2];
                #pragma unroll
                for (int p = 0; p < 2; p++)
                    ldsm4(bl[2*p][0], bl[2*p][1], bl[2*p+1][0], bl[2*p+1][1],
                          sWl + (b_row + p * 16) * RSTRIDE + ks * 32 + b_koff);
                #pragma unroll
                for (int i = 0; i < 4; i++)
                    #pragma unroll
                    for (int j = 0; j < 4; j++)
                        mma16816(acc[i][j], ah[i][0], ah[i][1], ah[i][2], ah[i][3],
                                 bl[j][0], bl[j][1]);
            }
        }
    }
    __syncthreads();

    // ---------------- epilogues ----------------
    if (z == 0) {
        const float* bias = b0v;
        float pr[4][2];
        #pragma unroll
        for (int i = 0; i < 4; i++) { pr[i][0] = 0.f; pr[i][1] = 0.f; }

        #pragma unroll
        for (int j = 0; j < 4; j++) {
            const int cb = bn + wn * 32 + j * 8 + (lane & 3) * 2;
            const float bi0 = __ldg(bias + cb),  bi1 = __ldg(bias + cb + 1);
            const float w0  = __ldg(rh + cb),    w1  = __ldg(rh + cb + 1);
            #pragma unroll
            for (int i = 0; i < 4; i++) {
                const float* c = acc[i][j];
                pr[i][0] += fmaxf(c[0] + bi0, 0.f) * w0 + fmaxf(c[1] + bi1, 0.f) * w1;
                pr[i][1] += fmaxf(c[2] + bi0, 0.f) * w0 + fmaxf(c[3] + bi1, 0.f) * w1;
            }
        }
        float* spart = (float*)smem;       // [128][4]
        #pragma unroll
        for (int i = 0; i < 4; i++)
            #pragma unroll
            for (int hh = 0; hh < 2; hh++) {
                float v = pr[i][hh];
                v += __shfl_xor_sync(0xffffffffu, v, 1);
                v += __shfl_xor_sync(0xffffffffu, v, 2);
                if ((lane & 3) == 0) {
                    const int row = wr * 64 + i * 16 + (lane >> 2) + hh * 8;
                    spart[row * 4 + wn] = v;
                }
            }
        __syncthreads();
        const int row = tid >> 1, hs = tid & 1;
        const float s = spart[row * 4 + hs * 2] + spart[row * 4 + hs * 2 + 1];
        const int m = bm + row, b = m >> 9, l = m & 511;
        g_scores[(b * NH + blockIdx.y * 2 + hs) * LEN + l] = s;
    } else {
        const float* bias = b1v;
        #pragma unroll
        for (int i = 0; i < 4; i++) {
            const int r0 = bm + wr * 64 + i * 16 + (lane >> 2);
            #pragma unroll
            for (int j = 0; j < 4; j++) {
                const int col = bn + wn * 32 + j * 8 + (lane & 3) * 2;
                const float bi0 = __ldg(bias + col), bi1 = __ldg(bias + col + 1);
                const float* c = acc[i][j];
                const __half2 h0 = __floats2half2_rn(fmaxf(c[0] + bi0, 0.f),
                                                     fmaxf(c[1] + bi1, 0.f));
                const __half2 h1 = __floats2half2_rn(fmaxf(c[2] + bi0, 0.f),
                                                     fmaxf(c[3] + bi1, 0.f));
                *(__half2*)&g_V1h[(size_t)r0 * GN + col]       = h0;
                *(__half2*)&g_V1h[(size_t)(r0 + 8) * GN + col] = h1;
            }
        }
    }
}

// ---------------- Kernel 2: fully parallel scan (R11-proven) -------------------
#define BIGV (1 << 30)
__global__ void scan_kernel()
{
    const int bh = blockIdx.x;
    const int t  = threadIdx.x;           // = l
    const int lane = t & 31, w = t >> 5;

    __shared__ float red[16];
    __shared__ int evsm[LEN];
    __shared__ int c0s[LEN];
    __shared__ int c1s[LEN];
    __shared__ int pos[LEN + 1];
    __shared__ int wsum[16], wmax[16], wmin[16];

    const float x = g_scores[bh * LEN + t];

    float v = x;
    #pragma unroll
    for (int o = 16; o; o >>= 1) v = fmaxf(v, __shfl_xor_sync(0xffffffffu, v, o));
    if (lane == 0) red[w] = v;
    __syncthreads();
    float m = red[0];
    #pragma unroll
    for (int i = 1; i < 16; i++) m = fmaxf(m, red[i]);
    __syncthreads();

    const float e = expf(x - m);
    float sv = e;
    #pragma unroll
    for (int o = 16; o; o >>= 1) sv += __shfl_xor_sync(0xffffffffu, sv, o);
    if (lane == 0) red[w] = sv;
    __syncthreads();
    float s = 0.f;
    #pragma unroll
    for (int i = 0; i < 16; i++) s += red[i];

    const float p = e / s + expf(-m);
    const int ev = (p > (1.5f / 512.0f)) ? 1 : 0;
    evsm[t] = ev;
    __syncthreads();

    int r  = (t >= 1) ? ev : 0;           // rank: events in 1..l
    int m0 = ev ? t : -1;                 // prefix max of event index
    #pragma unroll
    for (int o = 1; o < 32; o <<= 1) {
        const int nr = __shfl_up_sync(0xffffffffu, r, o);
        const int nm = __shfl_up_sync(0xffffffffu, m0, o);
        if (lane >= o) { r += nr; m0 = (nm > m0) ? nm : m0; }
    }
    const int rolled = (t < LEN - 1) ? evsm[t + 1] : evsm[0];
    int m1 = rolled ? t : BIGV;           // suffix min of rolled-event index
    #pragma unroll
    for (int o = 1; o < 32; o <<= 1) {
        const int nm = __shfl_down_sync(0xffffffffu, m1, o);
        if (lane + o < 32) m1 = (nm < m1) ? nm : m1;
    }
    if (lane == 31) { wsum[w] = r; wmax[w] = m0; }
    if (lane == 0)  { wmin[w] = m1; }
    __syncthreads();

    int sumoff = 0, maxoff = -1, minoff = BIGV;
    #pragma unroll
    for (int i = 0; i < 16; i++) {
        if (i < w) {
            sumoff += wsum[i];
            maxoff = (wmax[i] > maxoff) ? wmax[i] : maxoff;
        }
        if (i > w) minoff = (wmin[i] < minoff) ? wmin[i] : minoff;
    }
    const int rank = r + sumoff;
    const int M0 = (maxoff > m0) ? maxoff : m0;
    const int M1 = (minoff < m1) ? minoff : m1;
    const int c0 = (M0 >= 0) ? M0 : t;
    int c1 = (M1 < BIGV) ? (M1 + 1) : (t + 1);
    if (t == 0) c1 = 0;
    c0s[t] = c0;
    c1s[t] = c1;
    if (t >= 1 && ev) pos[rank] = t;
    __syncthreads();

    int vals[16];
    #pragma unroll
    for (int j = 0; j < 8; j++) {
        const int k = rank - j;
        int f = 0, b = 0;
        if (k >= 1) { const int pp = pos[k]; f = c0s[pp - 1]; b = c1s[pp - 1]; }
        vals[2 * j]     = (f > LEN - 1) ? LEN - 1 : f;
        vals[2 * j + 1] = (b > LEN - 1) ? LEN - 1 : b;
    }
    int4* dst = (int4*)(g_idx + (size_t)bh * LEN * R2V + t * R2V);
    dst[0] = make_int4(vals[0],  vals[1],  vals[2],  vals[3]);
    dst[1] = make_int4(vals[4],  vals[5],  vals[6],  vals[7]);
    dst[2] = make_int4(vals[8],  vals[9],  vals[10], vals[11]);
    dst[3] = make_int4(vals[12], vals[13], vals[14], vals[15]);
}

// ---------------- Kernel 3: gather 16 fp16 V rows + weighted sum ---------------
__global__ void gather_kernel(const float* __restrict__ w, float* __restrict__ out)
{
    const int b = blockIdx.z;
    const int h = blockIdx.y;
    const int lgrp = threadIdx.x >> 4;
    const int l = blockIdx.x * 16 + lgrp;
    const int j = threadIdx.x & 15;

    __shared__ float ws[R2V];
    if (threadIdx.x < R2V) ws[threadIdx.x] = w[h * R2V + threadIdx.x];
    __syncthreads();

    const int myidx = g_idx[(((size_t)(b * NH + h) * LEN + l) * R2V) + j];
    const __half* Vb = g_V1h + (size_t)b * LEN * GN + h * HD;

    float4 acc = make_float4(0.f, 0.f, 0.f, 0.f);
    #pragma unroll
    for (int r = 0; r < R2V; r++) {
        const int src = (threadIdx.x & 16) + r;
        const int rowi = __shfl_sync(0xffffffffu, myidx, src, 32);
        const float wr = ws[r];
        const uint2 raw = *(const uint2*)(Vb + (size_t)rowi * GN + j * 4);
        const float2 va = __half22float2(*reinterpret_cast<const __half2*>(&raw.x));
        const float2 vb = __half22float2(*reinterpret_cast<const __half2*>(&raw.y));
        acc.x += wr * va.x; acc.y += wr * va.y;
        acc.z += wr * vb.x; acc.w += wr * vb.y;
    }
    float* op = out + (((size_t)(b * LEN + l) * NH + h) * HD) + j * 4;
    *(float4*)op = acc;
}

// ---------------- launch -------------------------------------------------------
extern "C" void kernel_launch(void* const* d_in, const int* in_sizes, int n_in,
                              void* d_out, int out_size)
{
    const float* hs  = (const float*)d_in[0];
    const float* K1w = (const float*)d_in[1];
    const float* K1b = (const float*)d_in[2];
    const float* V1w = (const float*)d_in[3];
    const float* V1b = (const float*)d_in[4];
    const float* rh  = (const float*)d_in[5];
    const float* bw  = (const float*)d_in[6];
    float* out = (float*)d_out;

    cudaFuncSetAttribute(gemm_mma_kernel,
                         cudaFuncAttributeMaxDynamicSharedMemorySize, SMEMB);

    convert_kernel<<<(NA4 + 2 * NW4) / 256, 256>>>(hs, K1w, V1w);

    dim3 gg(GM / 128, GN / 128, 2);                       // 64 x 6 x 2
    gemm_mma_kernel<<<gg, 256, SMEMB>>>(K1b, V1b, rh);

    scan_kernel<<<BSZ * NH, 512>>>();

    dim3 g4(LEN / 16, NH, BSZ);
    gather_kernel<<<g4, 256>>>(bw, out);
}